// round 1
// baseline (speedup 1.0000x reference)
#include <cuda_runtime.h>
#include <cuda_bf16.h>

// Problem constants (fixed by the dataset): G=128 groups, NP=256 points/group,
// DD=256 feature dim. G is re-derived from in_sizes at launch for safety.
#define DD 256
#define NP 256
#define MAXG 128

#define RT 64    // rows of the C tile processed per pass
#define KT 32    // k-chunk
#define TPB 256  // threads per block

// Scratch (no cudaMalloc allowed): squared norms + per-block partial sums.
__device__ float g_xn[MAXG * NP];
__device__ float g_yn[MAXG * NP];
__device__ float g_part[3 * MAXG];

// ---------------------------------------------------------------------------
// Pass 1: squared norms, one warp per point row (coalesced float4 reads).
// ---------------------------------------------------------------------------
__global__ void norms_kernel(const float* __restrict__ x,
                             const float* __restrict__ y, int rows) {
    int warp = blockIdx.x * (blockDim.x >> 5) + (threadIdx.x >> 5);
    int lane = threadIdx.x & 31;
    int total = 2 * rows;
    if (warp >= total) return;
    const float* src = (warp < rows) ? x : y;
    float* dst       = (warp < rows) ? g_xn : g_yn;
    int row          = (warp < rows) ? warp : warp - rows;

    const float4* p = (const float4*)(src + (size_t)row * DD);
    float s = 0.f;
#pragma unroll
    for (int q = 0; q < DD / 4 / 32; q++) {     // 2 float4 per lane
        float4 v = p[lane + 32 * q];
        s += v.x * v.x + v.y * v.y + v.z * v.z + v.w * v.w;
    }
#pragma unroll
    for (int o = 16; o; o >>= 1) s += __shfl_xor_sync(0xffffffffu, s, o);
    if (lane == 0) dst[row] = s;
}

// ---------------------------------------------------------------------------
// Pass 2: one block per (group, matrix-type). Computes
//   sum_{i,j} sqrt(max(||a_i||^2 + ||b_j||^2 - 2 a_i.b_j, 0))
// with a register-tiled fp32 GEMM core (16x4 micro-tile per thread).
// ---------------------------------------------------------------------------
__global__ __launch_bounds__(TPB)
void mmd_kernel(const float* __restrict__ x, const float* __restrict__ y,
                int G) {
    __shared__ float xs[RT * KT];        // [row][kk], stride 32 (broadcast reads)
    __shared__ float ys[KT * 257];       // [kk][j], odd-ish stride 257 -> conflict-free transpose

    int bid = blockIdx.x;
    int t = bid % 3;          // 0: XY (+1), 1: XX (-0.5), 2: YY (-0.5)
    int g = bid / 3;

    const float *A, *B, *An, *Bn;
    float coeff;
    if (t == 0)      { A = x; B = y; An = g_xn; Bn = g_yn; coeff =  1.0f; }
    else if (t == 1) { A = x; B = x; An = g_xn; Bn = g_xn; coeff = -0.5f; }
    else             { A = y; B = y; An = g_yn; Bn = g_yn; coeff = -0.5f; }
    A  += (size_t)g * NP * DD;
    B  += (size_t)g * NP * DD;
    An += g * NP;
    Bn += g * NP;

    int tid  = threadIdx.x;
    int tx   = tid & 63;      // column group: owns columns tx, tx+64, tx+128, tx+192
    int ty   = tid >> 6;      // row group: owns 16 rows inside the 64-row tile
    int warp = tid >> 5;
    int lane = tid & 31;

    float b2[4];
#pragma unroll
    for (int c = 0; c < 4; c++) b2[c] = Bn[tx + 64 * c];

    float sum = 0.f;

    for (int r0 = 0; r0 < NP; r0 += RT) {
        float acc[16][4];
#pragma unroll
        for (int r = 0; r < 16; r++)
#pragma unroll
            for (int c = 0; c < 4; c++) acc[r][c] = 0.f;

        for (int k0 = 0; k0 < DD; k0 += KT) {
            // ---- load A tile: RT x KT = 2048 floats, 8 per thread, coalesced
#pragma unroll
            for (int q = 0; q < RT * KT / TPB; q++) {
                int e   = tid + q * TPB;
                int row = e >> 5;
                int kk  = e & 31;
                xs[row * KT + kk] = A[(r0 + row) * DD + k0 + kk];
            }
            // ---- load B tile transposed: ys[kk][j] = B[j][k0+kk]
            // warp handles 32 consecutive j rows; lane = kk -> coalesced LDG,
            // STS stride 257 -> bank-conflict-free.
#pragma unroll
            for (int q = 0; q < 32; q++) {
                int j = warp * 32 + q;
                ys[lane * 257 + j] = B[j * DD + k0 + lane];
            }
            __syncthreads();

#pragma unroll 4
            for (int kk = 0; kk < KT; kk++) {
                float yv0 = ys[kk * 257 + tx];
                float yv1 = ys[kk * 257 + tx + 64];
                float yv2 = ys[kk * 257 + tx + 128];
                float yv3 = ys[kk * 257 + tx + 192];
#pragma unroll
                for (int r = 0; r < 16; r++) {
                    float xv = xs[(ty * 16 + r) * KT + kk];  // broadcast
                    acc[r][0] += xv * yv0;
                    acc[r][1] += xv * yv1;
                    acc[r][2] += xv * yv2;
                    acc[r][3] += xv * yv3;
                }
            }
            __syncthreads();
        }

        // ---- epilogue: distances for this 64x256 C tile
#pragma unroll
        for (int r = 0; r < 16; r++) {
            float a2 = An[r0 + ty * 16 + r];
#pragma unroll
            for (int c = 0; c < 4; c++) {
                float d2 = a2 + b2[c] - 2.0f * acc[r][c];
                sum += sqrtf(fmaxf(d2, 0.0f));
            }
        }
    }

    // ---- deterministic block reduction
    __shared__ float red[TPB / 32];
#pragma unroll
    for (int o = 16; o; o >>= 1) sum += __shfl_xor_sync(0xffffffffu, sum, o);
    if (lane == 0) red[warp] = sum;
    __syncthreads();
    if (warp == 0) {
        float v = (lane < TPB / 32) ? red[lane] : 0.f;
#pragma unroll
        for (int o = 4; o; o >>= 1) v += __shfl_xor_sync(0xffffffffu, v, o);
        if (lane == 0) g_part[bid] = coeff * v;
    }
}

// ---------------------------------------------------------------------------
// Pass 3: deterministic final reduction of the 3*G partials.
// ---------------------------------------------------------------------------
__global__ void reduce_kernel(float* __restrict__ out, int G) {
    __shared__ float red[16];
    int tid = threadIdx.x;   // 512 threads
    float s = 0.f;
    for (int i = tid; i < 3 * G; i += blockDim.x) s += g_part[i];
#pragma unroll
    for (int o = 16; o; o >>= 1) s += __shfl_xor_sync(0xffffffffu, s, o);
    if ((tid & 31) == 0) red[tid >> 5] = s;
    __syncthreads();
    if (tid < 32) {
        float v = (tid < 16) ? red[tid] : 0.f;
#pragma unroll
        for (int o = 8; o; o >>= 1) v += __shfl_xor_sync(0xffffffffu, v, o);
        if (tid == 0)
            out[0] = v / ((float)NP * (float)NP * (float)G);
    }
}

// ---------------------------------------------------------------------------
extern "C" void kernel_launch(void* const* d_in, const int* in_sizes, int n_in,
                              void* d_out, int out_size) {
    const float* x = (const float*)d_in[0];
    const float* y = (const float*)d_in[1];
    // d_in[2] is the scalar "downsample" (256); shapes are compile-time here.
    int G = in_sizes[0] / (NP * DD);
    if (G > MAXG) G = MAXG;
    int rows = G * NP;

    int nwarps = 2 * rows;
    int nb = (nwarps + 7) / 8;                 // 8 warps (256 threads) / block
    norms_kernel<<<nb, 256>>>(x, y, rows);
    mmd_kernel<<<3 * G, TPB>>>(x, y, G);
    reduce_kernel<<<1, 512>>>((float*)d_out, G);
}

// round 6
// speedup vs baseline: 6.8735x; 6.8735x over previous
#include <cuda_runtime.h>
#include <cuda_fp16.h>
#include <cstdint>

#define DD 256          // feature dim
#define NP 256          // points per group
#define MAXG 128        // groups
#define TPB 256

// ---------------------------------------------------------------------------
// Scratch (no cudaMalloc allowed)
// ---------------------------------------------------------------------------
__device__ __half g_xh[MAXG * NP * DD];
__device__ __half g_yh[MAXG * NP * DD];
__device__ float g_xn[MAXG * NP], g_yn[MAXG * NP];
__device__ float g_part[10 * MAXG];

__device__ __forceinline__ uint32_t smem_u32(const void* p) {
    uint32_t a;
    asm("{ .reg .u64 t; cvta.to.shared.u64 t, %1; cvt.u32.u64 %0, t; }"
        : "=r"(a) : "l"(p));
    return a;
}

#define CP_ASYNC16(so, gp) \
    asm volatile("cp.async.cg.shared.global [%0], [%1], 16;" :: "r"(so), "l"(gp))
#define CP_COMMIT() asm volatile("cp.async.commit_group;" ::: "memory")
#define CP_WAIT0()  asm volatile("cp.async.wait_group 0;" ::: "memory")

#define LDSM_X4(r0, r1, r2, r3, addr) \
    asm volatile("ldmatrix.sync.aligned.m8n8.x4.shared.b16 {%0,%1,%2,%3}, [%4];" \
                 : "=r"(r0), "=r"(r1), "=r"(r2), "=r"(r3) : "r"(addr))

#define MMA16816(d, a, b) \
    asm volatile("mma.sync.aligned.m16n8k16.row.col.f32.f16.f16.f32 " \
                 "{%0,%1,%2,%3}, {%4,%5,%6,%7}, {%8,%9}, {%0,%1,%2,%3};" \
                 : "+f"((d)[0]), "+f"((d)[1]), "+f"((d)[2]), "+f"((d)[3]) \
                 : "r"((a)[0]), "r"((a)[1]), "r"((a)[2]), "r"((a)[3]), \
                   "r"((b)[0]), "r"((b)[1]))

// ---------------------------------------------------------------------------
// Pass 1: fp32 -> fp16 conversion + squared norms (fp32). One warp per row.
// ---------------------------------------------------------------------------
__global__ void prep_kernel(const float* __restrict__ x,
                            const float* __restrict__ y, int rows) {
    int warp = blockIdx.x * (blockDim.x >> 5) + (threadIdx.x >> 5);
    int lane = threadIdx.x & 31;
    if (warp >= 2 * rows) return;
    bool isx = warp < rows;
    int row  = isx ? warp : warp - rows;
    const float4* src = (const float4*)((isx ? x : y) + (size_t)row * DD);
    __half* hd = (isx ? g_xh : g_yh) + (size_t)row * DD;

    float s2 = 0.f;
#pragma unroll
    for (int q = 0; q < 2; q++) {
        float4 v = src[lane + 32 * q];
        __half2 h01 = __floats2half2_rn(v.x, v.y);
        __half2 h23 = __floats2half2_rn(v.z, v.w);
        uint2 pk;
        pk.x = *(uint32_t*)&h01;
        pk.y = *(uint32_t*)&h23;
        ((uint2*)hd)[lane + 32 * q] = pk;
        s2 += v.x * v.x + v.y * v.y + v.z * v.z + v.w * v.w;
    }
#pragma unroll
    for (int o = 16; o; o >>= 1) s2 += __shfl_xor_sync(0xffffffffu, s2, o);
    if (lane == 0) (isx ? g_xn : g_yn)[row] = s2;
}

// ---------------------------------------------------------------------------
// Stage loader: 128x64 fp16 A tile + 128x64 B tile, cp.async, xor-swizzled.
// smem row = 128 bytes; 16B chunk cc gets xor'ed with (row & 7).
// ---------------------------------------------------------------------------
__device__ __forceinline__ void stage_load(uint32_t sa, const __half* Ap,
                                           const __half* Bp, int tid) {
#pragma unroll
    for (int it = 0; it < 4; it++) {
        int e = tid + it * TPB;
        int r = e >> 3, cc = e & 7;
        uint32_t so = sa + (uint32_t)(r * 128 + ((cc ^ (r & 7)) << 4));
        CP_ASYNC16(so, Ap + (size_t)r * DD + cc * 8);
    }
    uint32_t sb = sa + 16384;
#pragma unroll
    for (int it = 0; it < 4; it++) {
        int e = tid + it * TPB;
        int r = e >> 3, cc = e & 7;
        uint32_t so = sb + (uint32_t)(r * 128 + ((cc ^ (r & 7)) << 4));
        CP_ASYNC16(so, Bp + (size_t)r * DD + cc * 8);
    }
}

// ---------------------------------------------------------------------------
// Pass 2: 128x128x256 fp16 HMMA GEMM + fused distance epilogue.
// grid = 10*G: per group, 4 XY blocks (w=1), 3 XX blocks, 3 YY blocks
// (symmetric off-diagonal blocks computed once with doubled weight).
// ---------------------------------------------------------------------------
__global__ __launch_bounds__(TPB, 2)
void gemm_kernel(int G) {
    extern __shared__ __align__(16) char dsmem[];   // 2 stages x 32KB
    __shared__ float an_s[128], bn_s[128], red[8];

    int bid = blockIdx.x;
    int g = bid / 10, blk = bid % 10;
    int t, mi, ni;
    float w;
    if (blk < 4) { t = 0; mi = blk >> 1; ni = blk & 1; w = 1.0f; }
    else {
        int q = blk - 4;
        t = 1 + q / 3;
        int r3 = q % 3;
        mi = (r3 == 2) ? 1 : 0;
        ni = (r3 == 0) ? 0 : 1;
        w = (r3 == 1) ? -1.0f : -0.5f;
    }
    const __half*  Ag = (t == 2) ? g_yh : g_xh;
    const __half*  Bg = (t == 0) ? g_yh : ((t == 1) ? g_xh : g_yh);
    const float*   An = (t == 2) ? g_yn : g_xn;
    const float*   Bn = (t == 0) ? g_yn : ((t == 1) ? g_xn : g_yn);
    const __half* Ap = Ag + ((size_t)g * NP + mi * 128) * DD;
    const __half* Bp = Bg + ((size_t)g * NP + ni * 128) * DD;

    int tid = threadIdx.x, wid = tid >> 5, lane = tid & 31;
    int wm = (wid & 1) * 64;        // warp M offset (2 warps in M)
    int wn = (wid >> 1) * 32;       // warp N offset (4 warps in N)

    if (tid < 128) an_s[tid] = An[g * NP + mi * 128 + tid];
    else           bn_s[tid - 128] = Bn[g * NP + ni * 128 + tid - 128];

    uint32_t s0 = smem_u32(dsmem);
    stage_load(s0, Ap, Bp, tid);
    CP_COMMIT();

    float acc[4][4][4];
#pragma unroll
    for (int a = 0; a < 4; a++)
#pragma unroll
        for (int b = 0; b < 4; b++)
#pragma unroll
            for (int c = 0; c < 4; c++) acc[a][b][c] = 0.f;

    for (int kb = 0; kb < 4; kb++) {              // 4 x KT=64
        CP_WAIT0();
        __syncthreads();
        if (kb < 3) {
            stage_load(s0 + ((kb + 1) & 1) * 32768,
                       Ap + (kb + 1) * 64, Bp + (kb + 1) * 64, tid);
            CP_COMMIT();
        }
        uint32_t ab = s0 + (kb & 1) * 32768;
        uint32_t bb = ab + 16384;

#pragma unroll
        for (int ks = 0; ks < 4; ks++) {          // 4 x k16 per stage
            int k0 = ks * 16;
            uint32_t af[4][4], bf[4][2];
            // A: 4 ldmatrix.x4 (non-trans), one per 16-row m-tile
            {
                int arow = wm + (lane & 15);
                int accc = (k0 >> 3) + (lane >> 4);
#pragma unroll
                for (int mt = 0; mt < 4; mt++) {
                    int row = arow + mt * 16;
                    uint32_t ad = ab + (uint32_t)(row * 128 + ((accc ^ (row & 7)) << 4));
                    LDSM_X4(af[mt][0], af[mt][1], af[mt][2], af[mt][3], ad);
                }
            }
            // B: 2 ldmatrix.x4 (non-trans, TN layout), covering 4 n-tiles
            {
                int brow0 = wn + (lane & 7) + ((lane >> 4) << 3);
                int bcc = (k0 >> 3) + ((lane >> 3) & 1);
#pragma unroll
                for (int p = 0; p < 2; p++) {
                    int row = brow0 + p * 16;
                    uint32_t bd = bb + (uint32_t)(row * 128 + ((bcc ^ (row & 7)) << 4));
                    uint32_t q0, q1, q2, q3;
                    LDSM_X4(q0, q1, q2, q3, bd);
                    bf[2 * p][0] = q0; bf[2 * p][1] = q1;
                    bf[2 * p + 1][0] = q2; bf[2 * p + 1][1] = q3;
                }
            }
#pragma unroll
            for (int mt = 0; mt < 4; mt++)
#pragma unroll
                for (int nt = 0; nt < 4; nt++)
                    MMA16816(acc[mt][nt], af[mt], bf[nt]);
        }
    }

    // ---- epilogue: d2 = |a|^2 + |b|^2 - 2 dot; skip exact diagonal for XX/YY
    bool diagblk = (t != 0) && (mi == ni);
    float sum = 0.f;
#pragma unroll
    for (int mt = 0; mt < 4; mt++) {
        int i0 = wm + mt * 16 + (lane >> 2);
        float an0 = an_s[i0], an1 = an_s[i0 + 8];
#pragma unroll
        for (int nt = 0; nt < 4; nt++) {
            int j0 = wn + nt * 8 + 2 * (lane & 3);
            float bn0 = bn_s[j0], bn1 = bn_s[j0 + 1];
            float* c = acc[mt][nt];
            float d00 = an0 + bn0 - 2.0f * c[0];
            float d01 = an0 + bn1 - 2.0f * c[1];
            float d10 = an1 + bn0 - 2.0f * c[2];
            float d11 = an1 + bn1 - 2.0f * c[3];
            float s00 = sqrtf(fmaxf(d00, 0.f));
            float s01 = sqrtf(fmaxf(d01, 0.f));
            float s10 = sqrtf(fmaxf(d10, 0.f));
            float s11 = sqrtf(fmaxf(d11, 0.f));
            if (diagblk) {
                if (i0 == j0)     s00 = 0.f;
                if (i0 == j0 + 1) s01 = 0.f;
                if (i0 + 8 == j0) s10 = 0.f;
                if (i0 + 8 == j0 + 1) s11 = 0.f;
            }
            sum += s00 + s01 + s10 + s11;
        }
    }

    // ---- deterministic block reduction
#pragma unroll
    for (int o = 16; o; o >>= 1) sum += __shfl_xor_sync(0xffffffffu, sum, o);
    if (lane == 0) red[wid] = sum;
    __syncthreads();
    if (wid == 0) {
        float v = (lane < 8) ? red[lane] : 0.f;
#pragma unroll
        for (int o = 4; o; o >>= 1) v += __shfl_xor_sync(0xffffffffu, v, o);
        if (lane == 0) g_part[bid] = w * v;
    }
}

// ---------------------------------------------------------------------------
// Pass 3: deterministic final reduction.
// ---------------------------------------------------------------------------
__global__ void reduce_kernel(float* __restrict__ out, int G) {
    __shared__ float red[16];
    int tid = threadIdx.x;
    float s = 0.f;
    for (int i = tid; i < 10 * G; i += blockDim.x) s += g_part[i];
#pragma unroll
    for (int o = 16; o; o >>= 1) s += __shfl_xor_sync(0xffffffffu, s, o);
    if ((tid & 31) == 0) red[tid >> 5] = s;
    __syncthreads();
    if (tid < 32) {
        float v = (tid < 16) ? red[tid] : 0.f;
#pragma unroll
        for (int o = 8; o; o >>= 1) v += __shfl_xor_sync(0xffffffffu, v, o);
        if (tid == 0) out[0] = v / ((float)NP * (float)NP * (float)G);
    }
}

// ---------------------------------------------------------------------------
extern "C" void kernel_launch(void* const* d_in, const int* in_sizes, int n_in,
                              void* d_out, int out_size) {
    const float* x = (const float*)d_in[0];
    const float* y = (const float*)d_in[1];
    int G = in_sizes[0] / (NP * DD);
    if (G > MAXG) G = MAXG;
    int rows = G * NP;

    static int smem_set = 0;
    if (!smem_set) {
        cudaFuncSetAttribute(gemm_kernel,
                             cudaFuncAttributeMaxDynamicSharedMemorySize, 65536);
        smem_set = 1;
    }

    prep_kernel<<<(2 * rows + 7) / 8, 256>>>(x, y, rows);
    gemm_kernel<<<10 * G, TPB, 65536>>>(G);
    reduce_kernel<<<1, 512>>>((float*)d_out, G);
}